// round 1
// baseline (speedup 1.0000x reference)
#include <cuda_runtime.h>
#include <math.h>

// HG2Vec fused loss:
//   per position p (B*L = 16384):
//     tgt = W_out[pos_u[p]]                       (D=300)
//     score_c = clip( cmask[c] * <tgt, W_in[pos_v[p,c]]>, +-10 ),  c<10
//     loss += sum_c log1p(exp(-score_c))
//     info_ci = clip( <W_out[pos_v[p,c]], W_in[info_v[p,i]]>, +-10 ) * sig[i]
//     loss += sum_ci log1p(exp(-info_ci)) * smask[i]
//
// Strategy: warp per (position, c-half). Each warp handles 5 contexts:
//  - per-lane float4 d-partition of the 300-dim rows (75 float4 per row)
//  - 35 register accumulators (5 score + 30 info), zero smem operand traffic
//  - duplicate tgt/info rows between the 2 warps of a position hit L1 (same CTA)
//  - butterfly shfl reduce, stage 35 sums via smem so the exp/log1p terms are
//    evaluated warp-parallel, then block partial -> scratch -> tree reduce.

#define DIM   300
#define NF4   75          // 300 floats = 75 float4 per row
#define NPOS  16384       // B*L
#define MAIN_BLOCKS 4096  // 8 warps/block, 2 warps/position -> 4 positions/block

__device__ float g_partial[MAIN_BLOCKS];

__global__ __launch_bounds__(256) void hg2vec_kernel(
    const int*   __restrict__ pos_u,
    const int*   __restrict__ pos_v,
    const int*   __restrict__ info_v,
    const float* __restrict__ W_in,
    const float* __restrict__ W_out,
    const float* __restrict__ cmask,
    const float* __restrict__ sig_mask,
    const float* __restrict__ score_mask)
{
    __shared__ float red[8][36];
    __shared__ float wloss[8];

    const int w    = threadIdx.x >> 5;
    const int lane = threadIdx.x & 31;
    const int gw   = blockIdx.x * 8 + w;   // global warp id, 0..32767
    const int p    = gw >> 1;              // position 0..16383
    const int grp  = gw & 1;               // which half of the 10 contexts

    // ---- gather indices ----
    const int pu = pos_u[p];
    int pv[5], iv[6];
#pragma unroll
    for (int c = 0; c < 5; c++) pv[c] = pos_v[p * 10 + grp * 5 + c];
#pragma unroll
    for (int i = 0; i < 6; i++) iv[i] = info_v[p * 6 + i];

    const float4* __restrict__ tgt = (const float4*)(W_out + (long)pu * DIM);
    const float4* cin4[5];
    const float4* cout4[5];
    const float4* inf4[6];
#pragma unroll
    for (int c = 0; c < 5; c++) {
        cin4[c]  = (const float4*)(W_in  + (long)pv[c] * DIM);
        cout4[c] = (const float4*)(W_out + (long)pv[c] * DIM);
    }
#pragma unroll
    for (int i = 0; i < 6; i++) inf4[i] = (const float4*)(W_in + (long)iv[i] * DIM);

    // ---- 35 accumulators: 5 score dots + 30 info dots ----
    float sc[5] = {0.f, 0.f, 0.f, 0.f, 0.f};
    float ai[30];
#pragma unroll
    for (int k = 0; k < 30; k++) ai[k] = 0.f;

#pragma unroll
    for (int jj = 0; jj < 3; jj++) {
        const int j = lane + jj * 32;
        if (j < NF4) {
            const float4 t4 = tgt[j];
            float4 f4[6];
#pragma unroll
            for (int i = 0; i < 6; i++) f4[i] = inf4[i][j];
#pragma unroll
            for (int c = 0; c < 5; c++) {
                const float4 a = cin4[c][j];
                sc[c] += a.x * t4.x + a.y * t4.y + a.z * t4.z + a.w * t4.w;
                const float4 b = cout4[c][j];
#pragma unroll
                for (int i = 0; i < 6; i++) {
                    ai[c * 6 + i] += b.x * f4[i].x + b.y * f4[i].y
                                   + b.z * f4[i].z + b.w * f4[i].w;
                }
            }
        }
    }

    // ---- butterfly reduce all 35 accumulators across the warp ----
#pragma unroll
    for (int off = 16; off; off >>= 1) {
#pragma unroll
        for (int c = 0; c < 5; c++)
            sc[c] += __shfl_xor_sync(0xffffffffu, sc[c], off);
#pragma unroll
        for (int k = 0; k < 30; k++)
            ai[k] += __shfl_xor_sync(0xffffffffu, ai[k], off);
    }

    // ---- stage reduced dots to smem (static reg indices), eval terms warp-parallel ----
    if (lane == 0) {
#pragma unroll
        for (int c = 0; c < 5; c++) red[w][c] = sc[c] * cmask[grp * 5 + c];
#pragma unroll
        for (int k = 0; k < 30; k++) red[w][5 + k] = ai[k];
    }
    __syncwarp();

    float loss = 0.f;
#pragma unroll
    for (int r = 0; r < 2; r++) {
        const int k = lane + r * 32;
        if (k < 35) {
            const float v = red[w][k];
            if (k < 5) {
                // score term: cmask already applied, clip then -logsigmoid
                const float x = fminf(fmaxf(v, -10.f), 10.f);
                loss += log1pf(expf(-x));
            } else {
                const int i = (k - 5) % 6;
                const float x = fminf(fmaxf(v, -10.f), 10.f) * sig_mask[i];
                loss += log1pf(expf(-x)) * score_mask[i];
            }
        }
    }

#pragma unroll
    for (int off = 16; off; off >>= 1)
        loss += __shfl_xor_sync(0xffffffffu, loss, off);

    if (lane == 0) wloss[w] = loss;
    __syncthreads();
    if (threadIdx.x == 0) {
        float s = 0.f;
#pragma unroll
        for (int q = 0; q < 8; q++) s += wloss[q];
        g_partial[blockIdx.x] = s;
    }
}

__global__ void hg2vec_reduce(float* __restrict__ out)
{
    __shared__ float s[256];
    float v = 0.f;
    for (int i = threadIdx.x; i < MAIN_BLOCKS; i += 256)
        v += g_partial[i];
    s[threadIdx.x] = v;
    __syncthreads();
#pragma unroll
    for (int st = 128; st; st >>= 1) {
        if (threadIdx.x < st) s[threadIdx.x] += s[threadIdx.x + st];
        __syncthreads();
    }
    if (threadIdx.x == 0) out[0] = s[0];
}

extern "C" void kernel_launch(void* const* d_in, const int* in_sizes, int n_in,
                              void* d_out, int out_size)
{
    const int*   pos_u  = (const int*)  d_in[0];
    const int*   pos_v  = (const int*)  d_in[1];
    const int*   info_v = (const int*)  d_in[2];
    const float* W_in   = (const float*)d_in[3];
    const float* W_out  = (const float*)d_in[4];
    const float* cmask  = (const float*)d_in[5];
    const float* sigm   = (const float*)d_in[6];
    const float* smask  = (const float*)d_in[7];

    hg2vec_kernel<<<MAIN_BLOCKS, 256>>>(pos_u, pos_v, info_v, W_in, W_out,
                                        cmask, sigm, smask);
    hg2vec_reduce<<<1, 256>>>((float*)d_out);
}